// round 2
// baseline (speedup 1.0000x reference)
#include <cuda_runtime.h>

#define Bn 32
#define Nn 4096
#define Kn 16
#define Dn 128
#define NBLK 16                 // N / 256 blocks per batch
#define GRIDA (Bn * NBLK)       // 512 blocks

// Deterministic scratch (no allocations allowed in kernel_launch)
__device__ float g_rec_partial[GRIDA];
__device__ float g_col_partial[GRIDA * Kn];

__global__ __launch_bounds__(256) void loss_main_kernel(
    const float* __restrict__ pc, const float* __restrict__ normals,
    const float* __restrict__ randn, const float* __restrict__ scale,
    const float* __restrict__ shapes, const float* __restrict__ rotate,
    const float* __restrict__ pam, const float* __restrict__ assign)
{
    __shared__ float sP[Kn * 17];      // per-k params: R(9), scale(3), e0,e1, mean(3)
    __shared__ float sA[256 * 17];     // padded assign rows (stride 17: conflict-free)
    __shared__ float scol[8 * Kn];     // per-warp column sums
    __shared__ float srec[8];

    const int blk  = blockIdx.x;
    const int b    = blk >> 4;
    const int nb   = blk & 15;
    const int t    = threadIdx.x;
    const int lane = t & 31;
    const int warp = t >> 5;
    const int n    = nb * 256 + t;

    // Stage per-(b,k) parameters
    if (t < 144) sP[(t / 9) * 17 + (t % 9)]      = rotate[b * 144 + t];
    if (t < 48)  sP[(t / 3) * 17 + 9 + (t % 3)]  = scale [b * 48  + t];
    if (t < 32)  sP[(t / 2) * 17 + 12 + (t % 2)] = shapes[b * 32  + t];
    if (t < 48)  sP[(t / 3) * 17 + 14 + (t % 3)] = pam   [b * 48  + t];

    // Stage this thread's assign row (16 floats) via 4x float4
    {
        const float4* ar = reinterpret_cast<const float4*>(assign) + ((size_t)b * Nn + n) * 4;
        float4 a0 = ar[0], a1 = ar[1], a2 = ar[2], a3 = ar[3];
        float* row = sA + t * 17;
        row[0]  = a0.x; row[1]  = a0.y; row[2]  = a0.z; row[3]  = a0.w;
        row[4]  = a1.x; row[5]  = a1.y; row[6]  = a1.z; row[7]  = a1.w;
        row[8]  = a2.x; row[9]  = a2.y; row[10] = a2.z; row[11] = a2.w;
        row[12] = a3.x; row[13] = a3.y; row[14] = a3.z; row[15] = a3.w;
    }
    __syncthreads();

    const size_t pi = ((size_t)b * Nn + n) * 3;
    const float px = pc[pi], py = pc[pi + 1], pz = pc[pi + 2];
    const float nx = normals[pi], ny = normals[pi + 1], nz = normals[pi + 2];
    const float r  = randn[b * Nn + n] * 0.01f;         // stop_gradient(randn) * W_STD
    const float sxp = px + r * nx, syp = py + r * ny, szp = pz + r * nz;  // pc_sample
    const float inl = rsqrtf(nx * nx + ny * ny + nz * nz);
    const float hx = nx * inl, hy = ny * inl, hz = nz * inl;              // unit normal

    float rec = 0.f;

    #pragma unroll 1
    for (int k = 0; k < Kn; k++) {
        const float* P = sP + k * 17;
        const float R0 = P[0], R1 = P[1], R2 = P[2], R3 = P[3], R4 = P[4],
                    R5 = P[5], R6 = P[6], R7 = P[7], R8 = P[8];
        const float s0 = P[9], s1 = P[10], s2 = P[11];
        const float e0 = P[12], e1 = P[13];
        const float mx = P[14], my = P[15], mz = P[16];

        // psi = R^T (pc_sample - mean)
        const float vx = sxp - mx, vy = syp - my, vz = szp - mz;
        const float q0 = R0 * vx + R3 * vy + R6 * vz;
        const float q1 = R1 * vx + R4 * vy + R7 * vz;
        const float q2 = R2 * vx + R5 * vy + R8 * vz;
        // pci = R^T (pc - mean)
        const float ux = px - mx, uy = py - my, uz = pz - mz;
        const float c0 = R0 * ux + R3 * uy + R6 * uz;
        const float c1 = R1 * ux + R4 * uy + R7 * uz;
        const float c2 = R2 * ux + R5 * uy + R8 * uz;
        // ni = R^T nhat
        const float w0 = R0 * hx + R3 * hy + R6 * hz;
        const float w1 = R1 * hx + R4 * hy + R7 * hz;
        const float w2 = R2 * hx + R5 * hy + R8 * hz;

        // argmax over 6 cube-face dots (first max wins, like jnp.argmax)
        float best = -w0; int idx = 0;
        if ( w1 == w1) {} // no-op keeps compiler honest on ordering
        if ( w0 > best) { best =  w0; idx = 1; }
        if (-w1 > best) { best = -w1; idx = 2; }
        if ( w1 > best) { best =  w1; idx = 3; }
        if (-w2 > best) { best = -w2; idx = 4; }
        if ( w2 > best) { best =  w2; idx = 5; }

        // project: replace axis coord with +/- scale, clip the rest
        float p0 = fminf(fmaxf(q0, -s0), s0);
        float p1 = fminf(fmaxf(q1, -s1), s1);
        float p2 = fminf(fmaxf(q2, -s2), s2);
        const float sgn = (idx & 1) ? 1.f : -1.f;
        const int   ax  = idx >> 1;
        if (ax == 0)      p0 = sgn * s0;
        else if (ax == 1) p1 = sgn * s1;
        else              p2 = sgn * s2;

        // sin/cos of atan2 computed algebraically (exact identity):
        //   theta = atan2(p1, p0): ct = p0/r, st = p1/r
        //   phi   = atan2(p2, r):  cp = r/rho, sp = p2/rho
        const float r2   = p0 * p0 + p1 * p1;
        const float rr   = sqrtf(r2);
        const float irho = rsqrtf(r2 + p2 * p2);   // rho^2 >= scale_ax^2 >= 0.01, never 0
        const float cp   = rr * irho;
        const float sp   = p2 * irho;
        const float irr  = rsqrtf(r2);             // inf if r2 == 0; guarded below
        const float ct   = (r2 > 0.f) ? p0 * irr : 1.f;   // atan2(0,0)=0 -> cos=1
        const float st   = (r2 > 0.f) ? p1 * irr : 0.f;

        // superquadric surface point: sign(x)*|x|^m
        const float gph = __powf(cp, e0);                             // cp >= 0
        const float fph = copysignf(__powf(fabsf(sp), e0), sp);
        const float gth = copysignf(__powf(fabsf(ct), e1), ct);
        const float fth = copysignf(__powf(fabsf(st), e1), st);

        const float X = s0 * gph * gth;
        const float Y = s1 * gph * fth;
        const float Z = s2 * fph;
        const float dx = X - c0, dy = Y - c1, dz = Z - c2;
        const float d  = dx * dx + dy * dy + dz * dz;

        const float ak = sA[t * 17 + k];
        rec += d * ak;

        // assign column partial (per warp, per k) — deterministic shuffle tree
        float csum = ak;
        #pragma unroll
        for (int off = 16; off; off >>= 1)
            csum += __shfl_down_sync(0xffffffffu, csum, off);
        if (lane == 0) scol[warp * Kn + k] = csum;
    }

    // REC block partial — deterministic tree
    #pragma unroll
    for (int off = 16; off; off >>= 1)
        rec += __shfl_down_sync(0xffffffffu, rec, off);
    if (lane == 0) srec[warp] = rec;
    __syncthreads();
    if (t == 0) {
        float s = 0.f;
        #pragma unroll
        for (int w = 0; w < 8; w++) s += srec[w];
        g_rec_partial[blk] = s;
    }
    if (t < Kn) {
        float s = 0.f;
        #pragma unroll
        for (int w = 0; w < 8; w++) s += scol[w * Kn + t];
        g_col_partial[blk * Kn + t] = s;
    }
}

__global__ __launch_bounds__(512) void loss_final_kernel(
    const float* __restrict__ exist, const float* __restrict__ mu,
    const float* __restrict__ logvar, const float* __restrict__ pam,
    const float* __restrict__ trans, float* __restrict__ out)
{
    __shared__ float sh[512];
    const int t = threadIdx.x;
    const int b = t >> 4, k = t & 15;

    auto bsum = [&](float v) -> float {
        sh[t] = v; __syncthreads();
        #pragma unroll
        for (int s = 256; s > 0; s >>= 1) {
            if (t < s) sh[t] += sh[t + s];
            __syncthreads();
        }
        float rv = sh[0]; __syncthreads();
        return rv;
    };

    // REC = grand sum / (B*N)
    const float REC = bsum(g_rec_partial[t]) * (1.0f / (32.f * 4096.f));

    // column sums of assign over n
    float cs = 0.f;
    #pragma unroll
    for (int nb = 0; nb < 16; nb++)
        cs += g_col_partial[((b * 16 + nb) * 16) + k];

    // SPS = mean_b ( mean_k sqrt(cs/N + 0.01) )^2
    const float sq = sqrtf(cs * (1.f / 4096.f) + 0.01f);
    sh[t] = sq; __syncthreads();
    float spsb = 0.f;
    if (t < 32) {
        float m = 0.f;
        #pragma unroll
        for (int kk = 0; kk < 16; kk++) m += sh[t * 16 + kk];
        m *= (1.f / 16.f);
        spsb = m * m;
    }
    __syncthreads();
    const float SPS = bsum((t < 32) ? spsb : 0.f) * (1.f / 32.f);

    // EXT = mean BCE-with-logits
    const float l  = exist[t];
    const float gt = (cs > 24.f) ? 1.f : 0.f;
    const float bce = fmaxf(l, 0.f) - l * gt + log1pf(expf(-fabsf(l)));
    const float EXT = bsum(bce) * (1.f / 512.f);

    // KLD = mean_b ( -0.5 * sum_d (1 + lv - mu^2 - exp(lv)) )
    float kl = 0.f;
    #pragma unroll
    for (int i = 0; i < 8; i++) {
        const int id = t * 8 + i;
        const float lv = logvar[id], m = mu[id];
        kl += 1.f + lv - m * m - expf(lv);
    }
    const float KLD = bsum(kl) * (-0.5f / 32.f);

    // CST = mean_{b,k} || mean - trans ||
    const float dx = pam[t * 3]     - trans[t * 3];
    const float dy = pam[t * 3 + 1] - trans[t * 3 + 1];
    const float dz = pam[t * 3 + 2] - trans[t * 3 + 2];
    const float CST = bsum(sqrtf(dx * dx + dy * dy + dz * dz)) * (1.f / 512.f);

    if (t == 0)
        out[0] = REC * 1.0f + SPS * 0.1f + EXT * 0.01f + KLD * 0.001f + CST * 0.1f;
}

extern "C" void kernel_launch(void* const* d_in, const int* in_sizes, int n_in,
                              void* d_out, int out_size)
{
    const float* pc      = (const float*)d_in[0];
    const float* normals = (const float*)d_in[1];
    const float* randn   = (const float*)d_in[2];
    const float* scale   = (const float*)d_in[3];
    const float* shapes  = (const float*)d_in[4];
    const float* rotate  = (const float*)d_in[5];
    const float* pam     = (const float*)d_in[6];
    const float* assign  = (const float*)d_in[7];
    const float* exist   = (const float*)d_in[8];
    const float* mu      = (const float*)d_in[9];
    const float* logvar  = (const float*)d_in[10];
    const float* trans   = (const float*)d_in[11];
    float* out = (float*)d_out;

    loss_main_kernel<<<GRIDA, 256>>>(pc, normals, randn, scale, shapes, rotate, pam, assign);
    loss_final_kernel<<<1, 512>>>(exist, mu, logvar, pam, trans, out);
}

// round 3
// speedup vs baseline: 1.0918x; 1.0918x over previous
#include <cuda_runtime.h>

#define Bn 32
#define Nn 4096
#define Kn 16
#define NBLK 16                 // N / 256 blocks per batch
#define GRIDA (Bn * NBLK)       // 512 blocks

// Deterministic scratch (no allocations allowed)
__device__ float g_rec_partial[GRIDA];
__device__ float g_col_partial[GRIDA * Kn];
__device__ unsigned int g_count = 0;

__global__ __launch_bounds__(256) void loss_fused_kernel(
    const float* __restrict__ pc, const float* __restrict__ normals,
    const float* __restrict__ randn, const float* __restrict__ scale,
    const float* __restrict__ shapes, const float* __restrict__ rotate,
    const float* __restrict__ pam, const float* __restrict__ assign,
    const float* __restrict__ exist, const float* __restrict__ mu,
    const float* __restrict__ logvar, const float* __restrict__ trans,
    float* __restrict__ out)
{
    __shared__ float sP[Kn * 17];      // per-k params: R(9), scale(3), e0,e1, mean(3)
    __shared__ float sA[256 * 17];     // padded assign rows (stride 17: conflict-free)
    __shared__ float scol2[256];       // per-(k,chunk) column partials
    __shared__ float srec[8];
    __shared__ float sfin[512];        // final-pass scratch
    __shared__ bool  isLast;

    const int blk  = blockIdx.x;
    const int b    = blk >> 4;
    const int nb   = blk & 15;
    const int t    = threadIdx.x;
    const int lane = t & 31;
    const int warp = t >> 5;
    const int n    = nb * 256 + t;

    // Stage per-(b,k) parameters
    if (t < 144) sP[(t / 9) * 17 + (t % 9)]      = rotate[b * 144 + t];
    if (t < 48)  sP[(t / 3) * 17 + 9 + (t % 3)]  = scale [b * 48  + t];
    if (t < 32)  sP[(t / 2) * 17 + 12 + (t % 2)] = shapes[b * 32  + t];
    if (t < 48)  sP[(t / 3) * 17 + 14 + (t % 3)] = pam   [b * 48  + t];

    // Stage this thread's assign row (16 floats) via 4x float4
    {
        const float4* ar = reinterpret_cast<const float4*>(assign) + ((size_t)b * Nn + n) * 4;
        float4 a0 = ar[0], a1 = ar[1], a2 = ar[2], a3 = ar[3];
        float* row = sA + t * 17;
        row[0]  = a0.x; row[1]  = a0.y; row[2]  = a0.z; row[3]  = a0.w;
        row[4]  = a1.x; row[5]  = a1.y; row[6]  = a1.z; row[7]  = a1.w;
        row[8]  = a2.x; row[9]  = a2.y; row[10] = a2.z; row[11] = a2.w;
        row[12] = a3.x; row[13] = a3.y; row[14] = a3.z; row[15] = a3.w;
    }
    __syncthreads();

    const size_t pi = ((size_t)b * Nn + n) * 3;
    const float px = pc[pi], py = pc[pi + 1], pz = pc[pi + 2];
    const float nx = normals[pi], ny = normals[pi + 1], nz = normals[pi + 2];
    const float r  = randn[b * Nn + n] * 0.01f;
    const float sxp = px + r * nx, syp = py + r * ny, szp = pz + r * nz;
    const float inl = rsqrtf(nx * nx + ny * ny + nz * nz);
    const float hx = nx * inl, hy = ny * inl, hz = nz * inl;

    float rec = 0.f;

    #pragma unroll 1
    for (int k = 0; k < Kn; k++) {
        const float* P = sP + k * 17;
        const float R0 = P[0], R1 = P[1], R2 = P[2], R3 = P[3], R4 = P[4],
                    R5 = P[5], R6 = P[6], R7 = P[7], R8 = P[8];
        const float s0 = P[9], s1 = P[10], s2 = P[11];
        const float e0 = P[12], e1 = P[13];
        const float mx = P[14], my = P[15], mz = P[16];

        const float vx = sxp - mx, vy = syp - my, vz = szp - mz;
        const float q0 = R0 * vx + R3 * vy + R6 * vz;
        const float q1 = R1 * vx + R4 * vy + R7 * vz;
        const float q2 = R2 * vx + R5 * vy + R8 * vz;
        const float ux = px - mx, uy = py - my, uz = pz - mz;
        const float c0 = R0 * ux + R3 * uy + R6 * uz;
        const float c1 = R1 * ux + R4 * uy + R7 * uz;
        const float c2 = R2 * ux + R5 * uy + R8 * uz;
        const float w0 = R0 * hx + R3 * hy + R6 * hz;
        const float w1 = R1 * hx + R4 * hy + R7 * hz;
        const float w2 = R2 * hx + R5 * hy + R8 * hz;

        // argmax over 6 cube-face dots (first max wins)
        float best = -w0; int idx = 0;
        if ( w0 > best) { best =  w0; idx = 1; }
        if (-w1 > best) { best = -w1; idx = 2; }
        if ( w1 > best) { best =  w1; idx = 3; }
        if (-w2 > best) { best = -w2; idx = 4; }
        if ( w2 > best) { best =  w2; idx = 5; }

        float p0 = fminf(fmaxf(q0, -s0), s0);
        float p1 = fminf(fmaxf(q1, -s1), s1);
        float p2 = fminf(fmaxf(q2, -s2), s2);
        const float sgn = (idx & 1) ? 1.f : -1.f;
        const int   ax  = idx >> 1;
        if (ax == 0)      p0 = sgn * s0;
        else if (ax == 1) p1 = sgn * s1;
        else              p2 = sgn * s2;

        // exact sin/cos of atan2 via identities
        const float r2   = p0 * p0 + p1 * p1;
        const float rr   = sqrtf(r2);
        const float irho = rsqrtf(r2 + p2 * p2);
        const float cp   = rr * irho;
        const float sp   = p2 * irho;
        const float irr  = rsqrtf(r2);
        const float ct   = (r2 > 0.f) ? p0 * irr : 1.f;
        const float st   = (r2 > 0.f) ? p1 * irr : 0.f;

        const float gph = __powf(cp, e0);
        const float fph = copysignf(__powf(fabsf(sp), e0), sp);
        const float gth = copysignf(__powf(fabsf(ct), e1), ct);
        const float fth = copysignf(__powf(fabsf(st), e1), st);

        const float X = s0 * gph * gth;
        const float Y = s1 * gph * fth;
        const float Z = s2 * fph;
        const float dx = X - c0, dy = Y - c1, dz = Z - c2;
        const float d  = dx * dx + dy * dy + dz * dz;

        rec += d * sA[t * 17 + k];
    }

    // --- block reductions (deterministic) ---
    #pragma unroll
    for (int off = 16; off; off >>= 1)
        rec += __shfl_down_sync(0xffffffffu, rec, off);
    if (lane == 0) srec[warp] = rec;

    // column sums of assign: thread t sums 16 rows of column (t&15), chunk (t>>4)
    {
        const int kcol = t & 15, chunk = t >> 4;
        float csum = 0.f;
        #pragma unroll
        for (int i = 0; i < 16; i++)
            csum += sA[(chunk * 16 + i) * 17 + kcol];
        scol2[t] = csum;
    }
    __syncthreads();

    if (t == 0) {
        float s = 0.f;
        #pragma unroll
        for (int w = 0; w < 8; w++) s += srec[w];
        g_rec_partial[blk] = s;
    }
    if (t < Kn) {
        float s = 0.f;
        #pragma unroll
        for (int c = 0; c < 16; c++) s += scol2[t + c * 16];
        g_col_partial[blk * Kn + t] = s;
    }

    // --- last-block-done: fused final reduction ---
    __threadfence();
    __syncthreads();
    if (t == 0) {
        unsigned int v = atomicAdd(&g_count, 1u);
        isLast = (v == GRIDA - 1);
    }
    __syncthreads();
    if (!isLast) return;
    __threadfence();

    float acc = 0.f;

    // REC: sum of 512 partials, each thread takes 2
    acc += (g_rec_partial[t] + g_rec_partial[t + 256]) * (1.0f / (32.f * 4096.f));

    // cs for (b,k) pairs p = t and p = t+256
    float cs0 = 0.f, cs1 = 0.f;
    {
        const int b0 = t >> 4,        k0 = t & 15;
        const int b1 = (t + 256) >> 4, k1 = t & 15;
        #pragma unroll
        for (int nb2 = 0; nb2 < 16; nb2++) {
            cs0 += g_col_partial[((b0 * 16 + nb2) << 4) + k0];
            cs1 += g_col_partial[((b1 * 16 + nb2) << 4) + k1];
        }
        sfin[t]       = sqrtf(cs0 * (1.f / 4096.f) + 0.01f);
        sfin[t + 256] = sqrtf(cs1 * (1.f / 4096.f) + 0.01f);
    }

    // EXT: BCE-with-logits for pairs t, t+256
    {
        const float l0 = exist[t],       l1 = exist[t + 256];
        const float g0 = (cs0 > 24.f) ? 1.f : 0.f;
        const float g1 = (cs1 > 24.f) ? 1.f : 0.f;
        const float e0v = fmaxf(l0, 0.f) - l0 * g0 + log1pf(expf(-fabsf(l0)));
        const float e1v = fmaxf(l1, 0.f) - l1 * g1 + log1pf(expf(-fabsf(l1)));
        acc += (e0v + e1v) * (0.01f / 512.f);
    }

    // KLD: 32*128 = 4096 elements, 16 per thread
    {
        float kl = 0.f;
        #pragma unroll
        for (int i = 0; i < 16; i++) {
            const int id = t * 16 + i;
            const float lv = logvar[id], m = mu[id];
            kl += 1.f + lv - m * m - expf(lv);
        }
        acc += kl * (-0.5f * 0.001f / 32.f);
    }

    // CST: 512 (b,k) pairs, 2 per thread
    {
        const int p0 = t, p1 = t + 256;
        float dx0 = pam[p0 * 3]     - trans[p0 * 3];
        float dy0 = pam[p0 * 3 + 1] - trans[p0 * 3 + 1];
        float dz0 = pam[p0 * 3 + 2] - trans[p0 * 3 + 2];
        float dx1 = pam[p1 * 3]     - trans[p1 * 3];
        float dy1 = pam[p1 * 3 + 1] - trans[p1 * 3 + 1];
        float dz1 = pam[p1 * 3 + 2] - trans[p1 * 3 + 2];
        acc += (sqrtf(dx0 * dx0 + dy0 * dy0 + dz0 * dz0) +
                sqrtf(dx1 * dx1 + dy1 * dy1 + dz1 * dz1)) * (0.1f / 512.f);
    }

    // SPS: needs per-b mean over k of sfin
    __syncthreads();
    if (t < 32) {
        float m = 0.f;
        #pragma unroll
        for (int kk = 0; kk < 16; kk++) m += sfin[t * 16 + kk];
        m *= (1.f / 16.f);
        acc += m * m * (0.1f / 32.f);
    }

    // block reduction of acc (256 threads)
    #pragma unroll
    for (int off = 16; off; off >>= 1)
        acc += __shfl_down_sync(0xffffffffu, acc, off);
    __syncthreads();               // sfin reads done before reuse of srec region
    if (lane == 0) srec[warp] = acc;
    __syncthreads();
    if (t == 0) {
        float s = 0.f;
        #pragma unroll
        for (int w = 0; w < 8; w++) s += srec[w];
        out[0] = s;
        g_count = 0;               // reset for next graph replay
    }
}

extern "C" void kernel_launch(void* const* d_in, const int* in_sizes, int n_in,
                              void* d_out, int out_size)
{
    const float* pc      = (const float*)d_in[0];
    const float* normals = (const float*)d_in[1];
    const float* randn   = (const float*)d_in[2];
    const float* scale   = (const float*)d_in[3];
    const float* shapes  = (const float*)d_in[4];
    const float* rotate  = (const float*)d_in[5];
    const float* pam     = (const float*)d_in[6];
    const float* assign  = (const float*)d_in[7];
    const float* exist   = (const float*)d_in[8];
    const float* mu      = (const float*)d_in[9];
    const float* logvar  = (const float*)d_in[10];
    const float* trans   = (const float*)d_in[11];
    float* out = (float*)d_out;

    loss_fused_kernel<<<GRIDA, 256>>>(pc, normals, randn, scale, shapes, rotate,
                                      pam, assign, exist, mu, logvar, trans, out);
}

// round 4
// speedup vs baseline: 1.4484x; 1.3266x over previous
#include <cuda_runtime.h>

#define Bn 32
#define Nn 4096
#define Kn 16
#define PTS 128                 // points per block
#define NBLK (Nn / PTS)         // 32 blocks per batch
#define GRIDA (Bn * NBLK)       // 1024 blocks

// Deterministic scratch (no allocations allowed)
__device__ float g_comb[GRIDA];             // rec + kld partial (pre-weighted)
__device__ float g_col_partial[GRIDA * Kn]; // assign column partials
__device__ unsigned int g_count = 0;

__device__ __forceinline__ float flog2(float x) {
    float y; asm("lg2.approx.f32 %0, %1;" : "=f"(y) : "f"(x)); return y;
}
__device__ __forceinline__ float fexp2(float x) {
    float y; asm("ex2.approx.f32 %0, %1;" : "=f"(y) : "f"(x)); return y;
}

__global__ __launch_bounds__(256) void loss_fused_kernel(
    const float* __restrict__ pc, const float* __restrict__ normals,
    const float* __restrict__ randn, const float* __restrict__ scale,
    const float* __restrict__ shapes, const float* __restrict__ rotate,
    const float* __restrict__ pam, const float* __restrict__ assign,
    const float* __restrict__ exist, const float* __restrict__ mu,
    const float* __restrict__ logvar, const float* __restrict__ trans,
    float* __restrict__ out)
{
    __shared__ float sP[Kn * 17];        // R(9), scale(3), he0, he1, mean(3)
    __shared__ float sA[PTS * 17];       // assign rows, stride-17 (conflict-free)
    __shared__ float scol2[256];
    __shared__ float srec[8];
    __shared__ float skld[4];
    __shared__ float sfin[512];
    __shared__ bool  isLast;

    const int blk   = blockIdx.x;
    const int b     = blk >> 5;          // batch
    const int t     = threadIdx.x;
    const int lane  = t & 31;
    const int warp  = t >> 5;
    const int nl    = t & (PTS - 1);     // local point id
    const int khalf = t >> 7;            // 0: k in [0,8), 1: k in [8,16)
    const int n     = (blk & 31) * PTS + nl;

    // Stage per-(b,k) parameters (he = 0.5 * shape exponent)
    if (t < 144) sP[(t / 9) * 17 + (t % 9)]      = rotate[b * 144 + t];
    if (t < 48)  sP[(t / 3) * 17 + 9 + (t % 3)]  = scale [b * 48  + t];
    if (t < 32)  sP[(t / 2) * 17 + 12 + (t % 2)] = 0.5f * shapes[b * 32 + t];
    if (t < 48)  sP[(t / 3) * 17 + 14 + (t % 3)] = pam   [b * 48  + t];

    // Stage assign rows: each thread loads half a row (8 floats)
    {
        const int row = t >> 1, half = t & 1;
        const float4* ar = reinterpret_cast<const float4*>(assign)
                         + ((size_t)b * Nn + (blk & 31) * PTS + row) * 4 + half * 2;
        float4 a0 = ar[0], a1 = ar[1];
        float* dst = sA + row * 17 + half * 8;
        dst[0] = a0.x; dst[1] = a0.y; dst[2] = a0.z; dst[3] = a0.w;
        dst[4] = a1.x; dst[5] = a1.y; dst[6] = a1.z; dst[7] = a1.w;
    }

    // KLD slice for this block: elems [blk*4, blk*4+4)
    if (t < 4) {
        const int id = blk * 4 + t;
        const float lv = logvar[id], m = mu[id];
        skld[t] = 1.f + lv - m * m - expf(lv);
    }
    __syncthreads();

    const size_t pi = ((size_t)b * Nn + n) * 3;
    const float px = pc[pi], py = pc[pi + 1], pz = pc[pi + 2];
    const float nx = normals[pi], ny = normals[pi + 1], nz = normals[pi + 2];
    const float nn  = nx * nx + ny * ny + nz * nz;
    const float inl = rsqrtf(nn);
    const float hx = nx * inl, hy = ny * inl, hz = nz * inl;   // unit normal
    // psi = pci + rn * (R^T nhat), rn = noise * ||normals||
    const float rn = randn[b * Nn + n] * 0.01f * nn * inl;

    float rec = 0.f;
    const float* arow = sA + nl * 17;

    #pragma unroll
    for (int kk = 0; kk < 8; kk++) {
        const int k = khalf * 8 + kk;
        const float* P = sP + k * 17;
        const float R0 = P[0], R1 = P[1], R2 = P[2], R3 = P[3], R4 = P[4],
                    R5 = P[5], R6 = P[6], R7 = P[7], R8 = P[8];
        const float s0 = P[9], s1 = P[10], s2 = P[11];
        const float he0 = P[12], he1 = P[13];
        const float mx = P[14], my = P[15], mz = P[16];

        // pci = R^T (pc - mean)
        const float ux = px - mx, uy = py - my, uz = pz - mz;
        const float c0 = R0 * ux + R3 * uy + R6 * uz;
        const float c1 = R1 * ux + R4 * uy + R7 * uz;
        const float c2 = R2 * ux + R5 * uy + R8 * uz;
        // w = R^T nhat
        const float w0 = R0 * hx + R3 * hy + R6 * hz;
        const float w1 = R1 * hx + R4 * hy + R7 * hz;
        const float w2 = R2 * hx + R5 * hy + R8 * hz;
        // psi = pci + rn * w
        const float q0 = fmaf(rn, w0, c0);
        const float q1 = fmaf(rn, w1, c1);
        const float q2 = fmaf(rn, w2, c2);

        // argmax over 6 faces == max |w| axis, sign = (w>0 ? + : -)
        const float a0 = fabsf(w0), a1 = fabsf(w1), a2 = fabsf(w2);
        int ax = 0; float best = a0;
        if (a1 > best) { best = a1; ax = 1; }
        if (a2 > best) { best = a2; ax = 2; }
        const float wax = (ax == 0) ? w0 : ((ax == 1) ? w1 : w2);
        const float sgn = (wax > 0.f) ? 1.f : -1.f;

        // clamp, then override selected axis with +/- scale
        float p0 = fminf(fmaxf(q0, -s0), s0);
        float p1 = fminf(fmaxf(q1, -s1), s1);
        float p2 = fminf(fmaxf(q2, -s2), s2);
        if (ax == 0)      p0 = sgn * s0;
        else if (ax == 1) p1 = sgn * s1;
        else              p2 = sgn * s2;

        // log-domain superquadric surface point
        const float p0sq = fmaxf(p0 * p0, 1e-38f);
        const float p1sq = fmaxf(p1 * p1, 1e-38f);
        const float p2sq = fmaxf(p2 * p2, 1e-38f);
        const float r2   = p0sq + p1sq;
        const float rho2 = r2 + p2sq;          // >= min(scale)^2 >= 0.01

        const float Lr  = flog2(r2);
        const float Lh  = flog2(rho2);
        const float L0  = flog2(p0sq);
        const float L1  = flog2(p1sq);
        const float L2  = flog2(p2sq);

        const float tphi = he0 * (Lr - Lh);            // log2(gph)
        const float u    = fmaf(-he1, Lr, tphi);
        const float X = copysignf(s0 * fexp2(fmaf(he1, L0, u)), p0);
        const float Y = copysignf(s1 * fexp2(fmaf(he1, L1, u)), p1);
        const float Z = copysignf(s2 * fexp2(he0 * (L2 - Lh)), p2);

        const float dx = X - c0, dy = Y - c1, dz = Z - c2;
        rec = fmaf(dx * dx + dy * dy + dz * dz, arow[k], rec);
    }

    // --- block reductions (deterministic) ---
    #pragma unroll
    for (int off = 16; off; off >>= 1)
        rec += __shfl_down_sync(0xffffffffu, rec, off);
    if (lane == 0) srec[warp] = rec;

    // assign column sums from sA: thread t sums 8 rows of column (t&15)
    {
        const int kcol = t & 15, chunk = t >> 4;   // 16 chunks x 8 rows = 128 rows
        float csum = 0.f;
        #pragma unroll
        for (int i = 0; i < 8; i++)
            csum += sA[(chunk * 8 + i) * 17 + kcol];
        scol2[t] = csum;
    }
    __syncthreads();

    if (t == 0) {
        float s = 0.f;
        #pragma unroll
        for (int w = 0; w < 8; w++) s += srec[w];
        float kp = skld[0] + skld[1] + skld[2] + skld[3];
        // pre-weight: REC coeff = W_REC/(B*N); KLD coeff = -0.5*W_KLD/B
        g_comb[blk] = s * (1.0f / (32.f * 4096.f)) + kp * (-0.5f * 0.001f / 32.f);
    }
    if (t < Kn) {
        float s = 0.f;
        #pragma unroll
        for (int c = 0; c < 16; c++) s += scol2[t + c * 16];
        g_col_partial[blk * Kn + t] = s;
    }

    // --- last-block-done: fused final reduction ---
    __threadfence();
    __syncthreads();
    if (t == 0) {
        unsigned int v = atomicAdd(&g_count, 1u);
        isLast = (v == GRIDA - 1);
    }
    __syncthreads();
    if (!isLast) return;
    __threadfence();

    float acc = g_comb[t] + g_comb[t + 256] + g_comb[t + 512] + g_comb[t + 768];

    // cs for (b,k) pairs p = t and p = t+256
    float cs0 = 0.f, cs1 = 0.f;
    {
        const int b0 = t >> 4, b1 = (t + 256) >> 4, kc = t & 15;
        #pragma unroll
        for (int nb2 = 0; nb2 < 32; nb2++) {
            cs0 += g_col_partial[((b0 * 32 + nb2) << 4) + kc];
            cs1 += g_col_partial[((b1 * 32 + nb2) << 4) + kc];
        }
        sfin[t]       = sqrtf(cs0 * (1.f / 4096.f) + 0.01f);
        sfin[t + 256] = sqrtf(cs1 * (1.f / 4096.f) + 0.01f);
    }

    // EXT: BCE-with-logits for pairs t, t+256 (weight 0.01)
    {
        const float l0 = exist[t], l1 = exist[t + 256];
        const float g0 = (cs0 > 24.f) ? 1.f : 0.f;
        const float g1 = (cs1 > 24.f) ? 1.f : 0.f;
        const float e0v = fmaxf(l0, 0.f) - l0 * g0 + log1pf(expf(-fabsf(l0)));
        const float e1v = fmaxf(l1, 0.f) - l1 * g1 + log1pf(expf(-fabsf(l1)));
        acc += (e0v + e1v) * (0.01f / 512.f);
    }

    // CST: 512 (b,k) pairs, 2 per thread (weight 0.1)
    {
        const int p0i = t * 3, p1i = (t + 256) * 3;
        float dx0 = pam[p0i]     - trans[p0i];
        float dy0 = pam[p0i + 1] - trans[p0i + 1];
        float dz0 = pam[p0i + 2] - trans[p0i + 2];
        float dx1 = pam[p1i]     - trans[p1i];
        float dy1 = pam[p1i + 1] - trans[p1i + 1];
        float dz1 = pam[p1i + 2] - trans[p1i + 2];
        acc += (sqrtf(dx0 * dx0 + dy0 * dy0 + dz0 * dz0) +
                sqrtf(dx1 * dx1 + dy1 * dy1 + dz1 * dz1)) * (0.1f / 512.f);
    }

    // SPS: per-b mean over k of sfin, squared (weight 0.1)
    __syncthreads();
    if (t < 32) {
        float m = 0.f;
        #pragma unroll
        for (int kk2 = 0; kk2 < 16; kk2++) m += sfin[t * 16 + kk2];
        m *= (1.f / 16.f);
        acc += m * m * (0.1f / 32.f);
    }

    // block reduction of acc
    #pragma unroll
    for (int off = 16; off; off >>= 1)
        acc += __shfl_down_sync(0xffffffffu, acc, off);
    __syncthreads();
    if (lane == 0) srec[warp] = acc;
    __syncthreads();
    if (t == 0) {
        float s = 0.f;
        #pragma unroll
        for (int w = 0; w < 8; w++) s += srec[w];
        out[0] = s;
        g_count = 0;   // reset for next graph replay
    }
}

extern "C" void kernel_launch(void* const* d_in, const int* in_sizes, int n_in,
                              void* d_out, int out_size)
{
    const float* pc      = (const float*)d_in[0];
    const float* normals = (const float*)d_in[1];
    const float* randn   = (const float*)d_in[2];
    const float* scale   = (const float*)d_in[3];
    const float* shapes  = (const float*)d_in[4];
    const float* rotate  = (const float*)d_in[5];
    const float* pam     = (const float*)d_in[6];
    const float* assign  = (const float*)d_in[7];
    const float* exist   = (const float*)d_in[8];
    const float* mu      = (const float*)d_in[9];
    const float* logvar  = (const float*)d_in[10];
    const float* trans   = (const float*)d_in[11];
    float* out = (float*)d_out;

    loss_fused_kernel<<<GRIDA, 256>>>(pc, normals, randn, scale, shapes, rotate,
                                      pam, assign, exist, mu, logvar, trans, out);
}